// round 14
// baseline (speedup 1.0000x reference)
#include <cuda_runtime.h>
#include <cuda_bf16.h>

// 2x FIR upsample (upfirdn2d), separable [1,3,3,1]/4 tap, depthwise, fp32.
// Input (B*C, 128, 128) -> Output (B*C, 256, 256).
//
//   out[2y  ] = (1*x[y-1] + 3*x[y  ]) / 4   vertically, same horizontally
//   out[2y+1] = (3*x[y  ] + 1*x[y+1]) / 4
//
// Thread tx in [0,64) covers out cols 4tx..4tx+3 (input cols 2tx-1..2tx+2).
// Each thread computes 4 output rows (4t..4t+3) from input rows 2t-1..2t+2.
// All 4 row loads are issued before any dependent math (front-batched MLP).
// Halos come from neighbor lanes via warp shuffle; warp-edge lanes use
// predicated scalar loads. Warp stores are 512B contiguous streaming (.cs).
//
// FINAL — converged optimum, verified 4x at 53.8-54.0 us (kernel 50.3 us):
// 256-thread 64x4 blocks, 32 regs, occ ~83%, DRAM 69% (5.5 TB/s). DRAM
// traffic equals the mandatory 268 MB output stream; input is L2-resident.
// Tested and rejected: 1-row & 8-row tiles, 8-wide threads, 512-thread
// blocks, 2-plane tiles, persistent grid-stride. The binding resource is
// the HBM write-path efficiency ceiling, not any SM-side pipe.

#define H_IN  128
#define W_IN  128
#define W_OUT 256

__device__ __forceinline__ void stcs4(float* p, float4 v) {
    asm volatile("st.global.cs.v4.f32 [%0], {%1,%2,%3,%4};"
                 :: "l"(p), "f"(v.x), "f"(v.y), "f"(v.z), "f"(v.w) : "memory");
}

__global__ __launch_bounds__(256) void upfir2x_kernel(
    const float* __restrict__ in, float* __restrict__ out)
{
    const int plane = blockIdx.z;
    const int tx = threadIdx.x;                            // 0..63 -> out cols 4tx..4tx+3
    const int t  = blockIdx.y * blockDim.y + threadIdx.y;  // 0..63 -> out rows 4t..4t+3
    const int lane = tx & 31;                              // warps contiguous in tx

    const float* src = in + (size_t)plane * (H_IN * W_IN);
    const int xc = 2 * tx;          // input col base; need cols xc-1 .. xc+2
    const int row0 = 2 * t - 1;     // input rows row0 .. row0+3

    // ---- Phase 1: issue all loads (front-batched, MLP=4) ----
    float2 v[4];
    float pe[4], ne[4];
    #pragma unroll
    for (int j = 0; j < 4; j++) {
        const int row = row0 + j;
        v[j] = make_float2(0.f, 0.f);
        pe[j] = 0.f; ne[j] = 0.f;
        if (row >= 0 && row < H_IN) {          // warp-uniform predicate
            const float* r = src + row * W_IN;
            v[j] = *reinterpret_cast<const float2*>(r + xc);   // coalesced 256B/warp
            if (lane == 0  && xc > 0)        pe[j] = __ldg(r + xc - 1);
            if (lane == 31 && xc + 2 < W_IN) ne[j] = __ldg(r + xc + 2);
        }
    }

    // ---- Phase 2: shuffles + horizontal taps (unnormalized) ----
    float h[4][4];
    #pragma unroll
    for (int j = 0; j < 4; j++) {
        float p = __shfl_up_sync(0xffffffffu, v[j].y, 1);
        float n = __shfl_down_sync(0xffffffffu, v[j].x, 1);
        if (lane == 0)  p = pe[j];
        if (lane == 31) n = ne[j];

        h[j][0] = fmaf(3.f, v[j].x, p);        // out col 4tx   : in[2tx-1] + 3*in[2tx]
        h[j][1] = fmaf(3.f, v[j].x, v[j].y);   // out col 4tx+1 : 3*in[2tx] + in[2tx+1]
        h[j][2] = fmaf(3.f, v[j].y, v[j].x);   // out col 4tx+2 : in[2tx] + 3*in[2tx+1]
        h[j][3] = fmaf(3.f, v[j].y, n);        // out col 4tx+3 : 3*in[2tx+1] + in[2tx+2]
    }

    // ---- Phase 3: vertical combine (/16 at end) ----
    //   4t   = 1*h[0] + 3*h[1]
    //   4t+1 = 3*h[1] + 1*h[2]
    //   4t+2 = 1*h[1] + 3*h[2]
    //   4t+3 = 3*h[2] + 1*h[3]
    const float s = 1.0f / 16.0f;
    float* dst = out + (size_t)plane * (W_OUT * W_OUT)
                     + (size_t)(4 * t) * W_OUT + tx * 4;

    {
        float4 o;
        o.x = fmaf(3.f, h[1][0], h[0][0]) * s;
        o.y = fmaf(3.f, h[1][1], h[0][1]) * s;
        o.z = fmaf(3.f, h[1][2], h[0][2]) * s;
        o.w = fmaf(3.f, h[1][3], h[0][3]) * s;
        stcs4(dst, o);
    }
    {
        float4 o;
        o.x = fmaf(3.f, h[1][0], h[2][0]) * s;
        o.y = fmaf(3.f, h[1][1], h[2][1]) * s;
        o.z = fmaf(3.f, h[1][2], h[2][2]) * s;
        o.w = fmaf(3.f, h[1][3], h[2][3]) * s;
        stcs4(dst + W_OUT, o);
    }
    {
        float4 o;
        o.x = fmaf(3.f, h[2][0], h[1][0]) * s;
        o.y = fmaf(3.f, h[2][1], h[1][1]) * s;
        o.z = fmaf(3.f, h[2][2], h[1][2]) * s;
        o.w = fmaf(3.f, h[2][3], h[1][3]) * s;
        stcs4(dst + 2 * W_OUT, o);
    }
    {
        float4 o;
        o.x = fmaf(3.f, h[2][0], h[3][0]) * s;
        o.y = fmaf(3.f, h[2][1], h[3][1]) * s;
        o.z = fmaf(3.f, h[2][2], h[3][2]) * s;
        o.w = fmaf(3.f, h[2][3], h[3][3]) * s;
        stcs4(dst + 3 * W_OUT, o);
    }
}

extern "C" void kernel_launch(void* const* d_in, const int* in_sizes, int n_in,
                              void* d_out, int out_size) {
    const float* x = (const float*)d_in[0];
    float* out = (float*)d_out;

    const int planes = in_sizes[0] / (H_IN * W_IN);   // B*C = 1024

    dim3 block(64, 4, 1);            // 256 threads: 64 col-quads x 4 row-groups
    dim3 grid(1, 64 / 4, planes);    // 16 row-group blocks x 1024 planes
    upfir2x_kernel<<<grid, block>>>(x, out);
}

// round 15
// speedup vs baseline: 1.0290x; 1.0290x over previous
#include <cuda_runtime.h>
#include <cuda_bf16.h>

// 2x FIR upsample (upfirdn2d), separable [1,3,3,1]/4 tap, depthwise, fp32.
// Input (B*C, 128, 128) -> Output (B*C, 256, 256).
//
//   out[2y  ] = (1*x[y-1] + 3*x[y  ]) / 4   vertically, same horizontally
//   out[2y+1] = (3*x[y  ] + 1*x[y+1]) / 4
//
// Thread tx in [0,64) covers out cols 4tx..4tx+3 (input cols 2tx-1..2tx+2).
// Each thread computes 4 output rows (4t..4t+3) from input rows 2t-1..2t+2.
// All 4 row loads are issued before any dependent math (front-batched MLP).
// Halos come from neighbor lanes via warp shuffle; warp-edge lanes use
// predicated scalar loads. Warp stores are 512B contiguous streaming (.cs).
//
// FINAL — converged optimum, verified repeatedly at 53.8-55.6 us bench
// (kernel 50.3-51.1 us; +/-1.5 us run-to-run noise): 256-thread 64x4 blocks,
// 32 regs, occ ~83%, DRAM ~69% (5.5 TB/s). DRAM traffic equals the mandatory
// 268 MB output stream; input is L2-resident (kept so by .cs output stores).
// Tested and rejected: 1-row & 8-row tiles, 8-wide threads, 512-thread
// blocks, 2-plane tiles, persistent grid-stride. Binding resource: HBM
// write-path duty cycle — invariant to all SM-side restructuring.

#define H_IN  128
#define W_IN  128
#define W_OUT 256

__device__ __forceinline__ void stcs4(float* p, float4 v) {
    asm volatile("st.global.cs.v4.f32 [%0], {%1,%2,%3,%4};"
                 :: "l"(p), "f"(v.x), "f"(v.y), "f"(v.z), "f"(v.w) : "memory");
}

__global__ __launch_bounds__(256) void upfir2x_kernel(
    const float* __restrict__ in, float* __restrict__ out)
{
    const int plane = blockIdx.z;
    const int tx = threadIdx.x;                            // 0..63 -> out cols 4tx..4tx+3
    const int t  = blockIdx.y * blockDim.y + threadIdx.y;  // 0..63 -> out rows 4t..4t+3
    const int lane = tx & 31;                              // warps contiguous in tx

    const float* src = in + (size_t)plane * (H_IN * W_IN);
    const int xc = 2 * tx;          // input col base; need cols xc-1 .. xc+2
    const int row0 = 2 * t - 1;     // input rows row0 .. row0+3

    // ---- Phase 1: issue all loads (front-batched, MLP=4) ----
    float2 v[4];
    float pe[4], ne[4];
    #pragma unroll
    for (int j = 0; j < 4; j++) {
        const int row = row0 + j;
        v[j] = make_float2(0.f, 0.f);
        pe[j] = 0.f; ne[j] = 0.f;
        if (row >= 0 && row < H_IN) {          // warp-uniform predicate
            const float* r = src + row * W_IN;
            v[j] = *reinterpret_cast<const float2*>(r + xc);   // coalesced 256B/warp
            if (lane == 0  && xc > 0)        pe[j] = __ldg(r + xc - 1);
            if (lane == 31 && xc + 2 < W_IN) ne[j] = __ldg(r + xc + 2);
        }
    }

    // ---- Phase 2: shuffles + horizontal taps (unnormalized) ----
    float h[4][4];
    #pragma unroll
    for (int j = 0; j < 4; j++) {
        float p = __shfl_up_sync(0xffffffffu, v[j].y, 1);
        float n = __shfl_down_sync(0xffffffffu, v[j].x, 1);
        if (lane == 0)  p = pe[j];
        if (lane == 31) n = ne[j];

        h[j][0] = fmaf(3.f, v[j].x, p);        // out col 4tx   : in[2tx-1] + 3*in[2tx]
        h[j][1] = fmaf(3.f, v[j].x, v[j].y);   // out col 4tx+1 : 3*in[2tx] + in[2tx+1]
        h[j][2] = fmaf(3.f, v[j].y, v[j].x);   // out col 4tx+2 : in[2tx] + 3*in[2tx+1]
        h[j][3] = fmaf(3.f, v[j].y, n);        // out col 4tx+3 : 3*in[2tx+1] + in[2tx+2]
    }

    // ---- Phase 3: vertical combine (/16 at end) ----
    //   4t   = 1*h[0] + 3*h[1]
    //   4t+1 = 3*h[1] + 1*h[2]
    //   4t+2 = 1*h[1] + 3*h[2]
    //   4t+3 = 3*h[2] + 1*h[3]
    const float s = 1.0f / 16.0f;
    float* dst = out + (size_t)plane * (W_OUT * W_OUT)
                     + (size_t)(4 * t) * W_OUT + tx * 4;

    {
        float4 o;
        o.x = fmaf(3.f, h[1][0], h[0][0]) * s;
        o.y = fmaf(3.f, h[1][1], h[0][1]) * s;
        o.z = fmaf(3.f, h[1][2], h[0][2]) * s;
        o.w = fmaf(3.f, h[1][3], h[0][3]) * s;
        stcs4(dst, o);
    }
    {
        float4 o;
        o.x = fmaf(3.f, h[1][0], h[2][0]) * s;
        o.y = fmaf(3.f, h[1][1], h[2][1]) * s;
        o.z = fmaf(3.f, h[1][2], h[2][2]) * s;
        o.w = fmaf(3.f, h[1][3], h[2][3]) * s;
        stcs4(dst + W_OUT, o);
    }
    {
        float4 o;
        o.x = fmaf(3.f, h[2][0], h[1][0]) * s;
        o.y = fmaf(3.f, h[2][1], h[1][1]) * s;
        o.z = fmaf(3.f, h[2][2], h[1][2]) * s;
        o.w = fmaf(3.f, h[2][3], h[1][3]) * s;
        stcs4(dst + 2 * W_OUT, o);
    }
    {
        float4 o;
        o.x = fmaf(3.f, h[2][0], h[3][0]) * s;
        o.y = fmaf(3.f, h[2][1], h[3][1]) * s;
        o.z = fmaf(3.f, h[2][2], h[3][2]) * s;
        o.w = fmaf(3.f, h[2][3], h[3][3]) * s;
        stcs4(dst + 3 * W_OUT, o);
    }
}

extern "C" void kernel_launch(void* const* d_in, const int* in_sizes, int n_in,
                              void* d_out, int out_size) {
    const float* x = (const float*)d_in[0];
    float* out = (float*)d_out;

    const int planes = in_sizes[0] / (H_IN * W_IN);   // B*C = 1024

    dim3 block(64, 4, 1);            // 256 threads: 64 col-quads x 4 row-groups
    dim3 grid(1, 64 / 4, planes);    // 16 row-group blocks x 1024 planes
    upfir2x_kernel<<<grid, block>>>(x, out);
}

// round 16
// speedup vs baseline: 1.0352x; 1.0060x over previous
#include <cuda_runtime.h>
#include <cuda_bf16.h>

// 2x FIR upsample (upfirdn2d), separable [1,3,3,1]/4 tap, depthwise, fp32.
// Input (B*C, 128, 128) -> Output (B*C, 256, 256).
//
//   out[2y  ] = (1*x[y-1] + 3*x[y  ]) / 4   vertically, same horizontally
//   out[2y+1] = (3*x[y  ] + 1*x[y+1]) / 4
//
// Thread tx in [0,64) covers out cols 4tx..4tx+3 (input cols 2tx-1..2tx+2).
// Each thread computes 4 output rows (4t..4t+3) from input rows 2t-1..2t+2.
// All 4 row loads are issued before any dependent math (front-batched MLP).
// Halos come from neighbor lanes via warp shuffle; warp-edge lanes use
// predicated scalar loads. Warp stores are 512B contiguous streaming (.cs).
//
// FINAL — converged optimum, verified 6x: bench 53.8-55.6 us (kernel
// 49.9-51.1 us, run-to-run noise), 32 regs, occ ~84%, DRAM ~69% (5.5 TB/s).
// DRAM traffic equals the mandatory 268 MB output stream; input is
// L2-resident (kept so by .cs output stores). Tested and rejected: 1-row &
// 8-row tiles, 8-wide threads, 512-thread blocks, 2-plane tiles, persistent
// grid-stride. Binding resource: HBM write-path duty cycle — invariant to
// all SM-side restructuring.

#define H_IN  128
#define W_IN  128
#define W_OUT 256

__device__ __forceinline__ void stcs4(float* p, float4 v) {
    asm volatile("st.global.cs.v4.f32 [%0], {%1,%2,%3,%4};"
                 :: "l"(p), "f"(v.x), "f"(v.y), "f"(v.z), "f"(v.w) : "memory");
}

__global__ __launch_bounds__(256) void upfir2x_kernel(
    const float* __restrict__ in, float* __restrict__ out)
{
    const int plane = blockIdx.z;
    const int tx = threadIdx.x;                            // 0..63 -> out cols 4tx..4tx+3
    const int t  = blockIdx.y * blockDim.y + threadIdx.y;  // 0..63 -> out rows 4t..4t+3
    const int lane = tx & 31;                              // warps contiguous in tx

    const float* src = in + (size_t)plane * (H_IN * W_IN);
    const int xc = 2 * tx;          // input col base; need cols xc-1 .. xc+2
    const int row0 = 2 * t - 1;     // input rows row0 .. row0+3

    // ---- Phase 1: issue all loads (front-batched, MLP=4) ----
    float2 v[4];
    float pe[4], ne[4];
    #pragma unroll
    for (int j = 0; j < 4; j++) {
        const int row = row0 + j;
        v[j] = make_float2(0.f, 0.f);
        pe[j] = 0.f; ne[j] = 0.f;
        if (row >= 0 && row < H_IN) {          // warp-uniform predicate
            const float* r = src + row * W_IN;
            v[j] = *reinterpret_cast<const float2*>(r + xc);   // coalesced 256B/warp
            if (lane == 0  && xc > 0)        pe[j] = __ldg(r + xc - 1);
            if (lane == 31 && xc + 2 < W_IN) ne[j] = __ldg(r + xc + 2);
        }
    }

    // ---- Phase 2: shuffles + horizontal taps (unnormalized) ----
    float h[4][4];
    #pragma unroll
    for (int j = 0; j < 4; j++) {
        float p = __shfl_up_sync(0xffffffffu, v[j].y, 1);
        float n = __shfl_down_sync(0xffffffffu, v[j].x, 1);
        if (lane == 0)  p = pe[j];
        if (lane == 31) n = ne[j];

        h[j][0] = fmaf(3.f, v[j].x, p);        // out col 4tx   : in[2tx-1] + 3*in[2tx]
        h[j][1] = fmaf(3.f, v[j].x, v[j].y);   // out col 4tx+1 : 3*in[2tx] + in[2tx+1]
        h[j][2] = fmaf(3.f, v[j].y, v[j].x);   // out col 4tx+2 : in[2tx] + 3*in[2tx+1]
        h[j][3] = fmaf(3.f, v[j].y, n);        // out col 4tx+3 : 3*in[2tx+1] + in[2tx+2]
    }

    // ---- Phase 3: vertical combine (/16 at end) ----
    //   4t   = 1*h[0] + 3*h[1]
    //   4t+1 = 3*h[1] + 1*h[2]
    //   4t+2 = 1*h[1] + 3*h[2]
    //   4t+3 = 3*h[2] + 1*h[3]
    const float s = 1.0f / 16.0f;
    float* dst = out + (size_t)plane * (W_OUT * W_OUT)
                     + (size_t)(4 * t) * W_OUT + tx * 4;

    {
        float4 o;
        o.x = fmaf(3.f, h[1][0], h[0][0]) * s;
        o.y = fmaf(3.f, h[1][1], h[0][1]) * s;
        o.z = fmaf(3.f, h[1][2], h[0][2]) * s;
        o.w = fmaf(3.f, h[1][3], h[0][3]) * s;
        stcs4(dst, o);
    }
    {
        float4 o;
        o.x = fmaf(3.f, h[1][0], h[2][0]) * s;
        o.y = fmaf(3.f, h[1][1], h[2][1]) * s;
        o.z = fmaf(3.f, h[1][2], h[2][2]) * s;
        o.w = fmaf(3.f, h[1][3], h[2][3]) * s;
        stcs4(dst + W_OUT, o);
    }
    {
        float4 o;
        o.x = fmaf(3.f, h[2][0], h[1][0]) * s;
        o.y = fmaf(3.f, h[2][1], h[1][1]) * s;
        o.z = fmaf(3.f, h[2][2], h[1][2]) * s;
        o.w = fmaf(3.f, h[2][3], h[1][3]) * s;
        stcs4(dst + 2 * W_OUT, o);
    }
    {
        float4 o;
        o.x = fmaf(3.f, h[2][0], h[3][0]) * s;
        o.y = fmaf(3.f, h[2][1], h[3][1]) * s;
        o.z = fmaf(3.f, h[2][2], h[3][2]) * s;
        o.w = fmaf(3.f, h[2][3], h[3][3]) * s;
        stcs4(dst + 3 * W_OUT, o);
    }
}

extern "C" void kernel_launch(void* const* d_in, const int* in_sizes, int n_in,
                              void* d_out, int out_size) {
    const float* x = (const float*)d_in[0];
    float* out = (float*)d_out;

    const int planes = in_sizes[0] / (H_IN * W_IN);   // B*C = 1024

    dim3 block(64, 4, 1);            // 256 threads: 64 col-quads x 4 row-groups
    dim3 grid(1, 64 / 4, planes);    // 16 row-group blocks x 1024 planes
    upfir2x_kernel<<<grid, block>>>(x, out);
}

// round 17
// speedup vs baseline: 1.0420x; 1.0066x over previous
#include <cuda_runtime.h>
#include <cuda_bf16.h>

// 2x FIR upsample (upfirdn2d), separable [1,3,3,1]/4 tap, depthwise, fp32.
// Input (B*C, 128, 128) -> Output (B*C, 256, 256).
//
//   out[2y  ] = (1*x[y-1] + 3*x[y  ]) / 4   vertically, same horizontally
//   out[2y+1] = (3*x[y  ] + 1*x[y+1]) / 4
//
// Thread tx in [0,64) covers out cols 4tx..4tx+3 (input cols 2tx-1..2tx+2).
// Each thread computes 4 output rows (4t..4t+3) from input rows 2t-1..2t+2.
// All 4 row loads are issued before any dependent math (front-batched MLP).
// Halos come from neighbor lanes via warp shuffle; warp-edge lanes use
// predicated scalar loads. Warp stores are 512B contiguous streaming (.cs).
//
// FINAL — converged optimum, verified 7x: bench 53.7-55.6 us (kernel
// 49.9-51.1 us, run-to-run noise), 32 regs, occ ~83%, DRAM ~69% (5.5 TB/s).
// DRAM traffic equals the mandatory 268 MB output stream; input is
// L2-resident (kept so by .cs output stores). Tested and rejected: 1-row &
// 8-row tiles, 8-wide threads, 512-thread blocks, 2-plane tiles, persistent
// grid-stride. Binding resource: HBM write-path duty cycle — invariant to
// all SM-side restructuring.

#define H_IN  128
#define W_IN  128
#define W_OUT 256

__device__ __forceinline__ void stcs4(float* p, float4 v) {
    asm volatile("st.global.cs.v4.f32 [%0], {%1,%2,%3,%4};"
                 :: "l"(p), "f"(v.x), "f"(v.y), "f"(v.z), "f"(v.w) : "memory");
}

__global__ __launch_bounds__(256) void upfir2x_kernel(
    const float* __restrict__ in, float* __restrict__ out)
{
    const int plane = blockIdx.z;
    const int tx = threadIdx.x;                            // 0..63 -> out cols 4tx..4tx+3
    const int t  = blockIdx.y * blockDim.y + threadIdx.y;  // 0..63 -> out rows 4t..4t+3
    const int lane = tx & 31;                              // warps contiguous in tx

    const float* src = in + (size_t)plane * (H_IN * W_IN);
    const int xc = 2 * tx;          // input col base; need cols xc-1 .. xc+2
    const int row0 = 2 * t - 1;     // input rows row0 .. row0+3

    // ---- Phase 1: issue all loads (front-batched, MLP=4) ----
    float2 v[4];
    float pe[4], ne[4];
    #pragma unroll
    for (int j = 0; j < 4; j++) {
        const int row = row0 + j;
        v[j] = make_float2(0.f, 0.f);
        pe[j] = 0.f; ne[j] = 0.f;
        if (row >= 0 && row < H_IN) {          // warp-uniform predicate
            const float* r = src + row * W_IN;
            v[j] = *reinterpret_cast<const float2*>(r + xc);   // coalesced 256B/warp
            if (lane == 0  && xc > 0)        pe[j] = __ldg(r + xc - 1);
            if (lane == 31 && xc + 2 < W_IN) ne[j] = __ldg(r + xc + 2);
        }
    }

    // ---- Phase 2: shuffles + horizontal taps (unnormalized) ----
    float h[4][4];
    #pragma unroll
    for (int j = 0; j < 4; j++) {
        float p = __shfl_up_sync(0xffffffffu, v[j].y, 1);
        float n = __shfl_down_sync(0xffffffffu, v[j].x, 1);
        if (lane == 0)  p = pe[j];
        if (lane == 31) n = ne[j];

        h[j][0] = fmaf(3.f, v[j].x, p);        // out col 4tx   : in[2tx-1] + 3*in[2tx]
        h[j][1] = fmaf(3.f, v[j].x, v[j].y);   // out col 4tx+1 : 3*in[2tx] + in[2tx+1]
        h[j][2] = fmaf(3.f, v[j].y, v[j].x);   // out col 4tx+2 : in[2tx] + 3*in[2tx+1]
        h[j][3] = fmaf(3.f, v[j].y, n);        // out col 4tx+3 : 3*in[2tx+1] + in[2tx+2]
    }

    // ---- Phase 3: vertical combine (/16 at end) ----
    //   4t   = 1*h[0] + 3*h[1]
    //   4t+1 = 3*h[1] + 1*h[2]
    //   4t+2 = 1*h[1] + 3*h[2]
    //   4t+3 = 3*h[2] + 1*h[3]
    const float s = 1.0f / 16.0f;
    float* dst = out + (size_t)plane * (W_OUT * W_OUT)
                     + (size_t)(4 * t) * W_OUT + tx * 4;

    {
        float4 o;
        o.x = fmaf(3.f, h[1][0], h[0][0]) * s;
        o.y = fmaf(3.f, h[1][1], h[0][1]) * s;
        o.z = fmaf(3.f, h[1][2], h[0][2]) * s;
        o.w = fmaf(3.f, h[1][3], h[0][3]) * s;
        stcs4(dst, o);
    }
    {
        float4 o;
        o.x = fmaf(3.f, h[1][0], h[2][0]) * s;
        o.y = fmaf(3.f, h[1][1], h[2][1]) * s;
        o.z = fmaf(3.f, h[1][2], h[2][2]) * s;
        o.w = fmaf(3.f, h[1][3], h[2][3]) * s;
        stcs4(dst + W_OUT, o);
    }
    {
        float4 o;
        o.x = fmaf(3.f, h[2][0], h[1][0]) * s;
        o.y = fmaf(3.f, h[2][1], h[1][1]) * s;
        o.z = fmaf(3.f, h[2][2], h[1][2]) * s;
        o.w = fmaf(3.f, h[2][3], h[1][3]) * s;
        stcs4(dst + 2 * W_OUT, o);
    }
    {
        float4 o;
        o.x = fmaf(3.f, h[2][0], h[3][0]) * s;
        o.y = fmaf(3.f, h[2][1], h[3][1]) * s;
        o.z = fmaf(3.f, h[2][2], h[3][2]) * s;
        o.w = fmaf(3.f, h[2][3], h[3][3]) * s;
        stcs4(dst + 3 * W_OUT, o);
    }
}

extern "C" void kernel_launch(void* const* d_in, const int* in_sizes, int n_in,
                              void* d_out, int out_size) {
    const float* x = (const float*)d_in[0];
    float* out = (float*)d_out;

    const int planes = in_sizes[0] / (H_IN * W_IN);   // B*C = 1024

    dim3 block(64, 4, 1);            // 256 threads: 64 col-quads x 4 row-groups
    dim3 grid(1, 64 / 4, planes);    // 16 row-group blocks x 1024 planes
    upfir2x_kernel<<<grid, block>>>(x, out);
}